// round 6
// baseline (speedup 1.0000x reference)
#include <cuda_runtime.h>
#include <cstdint>

#define NHEADS 16
#define HID    1024
#define TT     2048
#define BB     32

typedef unsigned long long ull;

// ---------------- device scratch (no allocations allowed) ----------------
__device__ float g_wq[NHEADS * HID];
__device__ float g_c[NHEADS];
__device__ float g_logits[BB * NHEADS * TT];          // raw logits
__device__ float2 g_stats[BB * NHEADS];               // (max, 1/sum) per (b,h)
__device__ float g_partial[16 * BB * NHEADS * HID];   // pooled partials (8 slices used)
__device__ float g_outv[BB * HID];
__device__ float g_fpart[16 * BB * HID];

#define FMA2(c, a, b) asm("fma.rn.f32x2 %0, %1, %2, %0;" : "+l"(c) : "l"(a), "l"(b))
static __device__ __forceinline__ float f2_lo(ull v) { return __uint_as_float((unsigned)(v & 0xffffffffull)); }
static __device__ __forceinline__ float f2_hi(ull v) { return __uint_as_float((unsigned)(v >> 32)); }

static __device__ __forceinline__ unsigned smaddr(const void* p) {
    return (unsigned)__cvta_generic_to_shared(p);
}
#define CP16(dst, src)  asm volatile("cp.async.cg.shared.global [%0], [%1], 16;" :: "r"(dst), "l"(src))
#define CP_COMMIT()     asm volatile("cp.async.commit_group;" ::: "memory")
#define CP_WAIT2()      asm volatile("cp.async.wait_group 2;" ::: "memory")

// ---------------- kernel 1: fold query into kv_w (k half) ----------------
__global__ void k_wq(const float* __restrict__ q,
                     const float* __restrict__ kvw,
                     const float* __restrict__ kvb) {
    int w = blockIdx.x * (blockDim.x >> 5) + (threadIdx.x >> 5);
    int lane = threadIdx.x & 31;
    if (w < NHEADS * HID) {
        int h = w & (NHEADS - 1);
        int i = w >> 4;
        const float* wr = kvw + (size_t)i * (2 * HID) + h * 64;
        const float* qr = q + h * 64;
        float s = qr[lane] * wr[lane] + qr[lane + 32] * wr[lane + 32];
        #pragma unroll
        for (int o = 16; o; o >>= 1) s += __shfl_xor_sync(0xffffffffu, s, o);
        if (lane == 0) g_wq[h * HID + i] = 0.125f * s;
    }
    if (blockIdx.x == 0 && threadIdx.x < NHEADS) {
        int h = threadIdx.x;
        float s = 0.f;
        for (int d = 0; d < 64; d++) s += q[h * 64 + d] * kvb[h * 64 + d];
        g_c[h] = 0.125f * s;
    }
}

// ---------------- kernel 2: logits ----------------
// 128 threads, TWO rows each (t, t+128). hid staged via cp.async into
// k4-major planes hid_c[stage][k4][256 rows] (float4) -> LDS.128 is
// contiguous across lanes = conflict-free. 3-stage ring, LCH=16.
// 48KB dynamic + 3KB static -> 4 CTAs = 16 warps/SM.
#define LCH 16
__global__ void __launch_bounds__(128) k_logits(const float* __restrict__ hid) {
    extern __shared__ __align__(16) float4 hid_c[];     // [3][4][256]
    __shared__ __align__(16) float wq_s[3][NHEADS][LCH];
    int tid = threadIdx.x;
    const float* hblk = hid + (size_t)blockIdx.x * 256 * HID;

    ull acc0[NHEADS], acc1[NHEADS];
    #pragma unroll
    for (int h = 0; h < NHEADS; h++) { acc0[h] = 0ull; acc1[h] = 0ull; }

    // fill helper pattern: stage st <- k chunk kc
    #define LFILL(st, kc)                                                          \
        do {                                                                       \
            _Pragma("unroll")                                                      \
            for (int p = 0; p < 8; p++) {                                          \
                int idx = p * 128 + tid;                                           \
                int k4  = idx >> 8;                                                \
                int row = idx & 255;                                               \
                CP16(smaddr(&hid_c[((st) * 4 + k4) * 256 + row]),                  \
                     hblk + (size_t)row * HID + (kc) + k4 * 4);                    \
            }                                                                      \
            if (tid < 64) {                                                        \
                int h  = tid >> 2;                                                 \
                int kq = (tid & 3) * 4;                                            \
                CP16(smaddr(&wq_s[st][h][kq]), g_wq + h * HID + (kc) + kq);        \
            }                                                                      \
        } while (0)

    LFILL(0, 0);  CP_COMMIT();
    LFILL(1, 16); CP_COMMIT();

    for (int c = 0; c < HID / LCH; c++) {
        if (c + 2 < HID / LCH) {
            int st = (c + 2) % 3;
            int kc = (c + 2) * LCH;
            LFILL(st, kc);
        }
        CP_COMMIT();
        CP_WAIT2();
        __syncthreads();

        int buf = c % 3;
        #pragma unroll
        for (int k4 = 0; k4 < 4; k4++) {
            ulonglong2 a0 = *(const ulonglong2*)&hid_c[(buf * 4 + k4) * 256 + tid];
            ulonglong2 a1 = *(const ulonglong2*)&hid_c[(buf * 4 + k4) * 256 + tid + 128];
            #pragma unroll
            for (int h = 0; h < NHEADS; h++) {
                ulonglong2 w = *(const ulonglong2*)&wq_s[buf][h][k4 * 4];
                FMA2(acc0[h], a0.x, w.x);
                FMA2(acc0[h], a0.y, w.y);
                FMA2(acc1[h], a1.x, w.x);
                FMA2(acc1[h], a1.y, w.y);
            }
        }
        __syncthreads();
    }

    size_t jA = (size_t)blockIdx.x * 256 + tid;
    size_t jB = jA + 128;
    int bA = (int)(jA >> 11), ja = (int)(jA & 2047);
    int bB = (int)(jB >> 11), jb = (int)(jB & 2047);
    #pragma unroll
    for (int h = 0; h < NHEADS; h++) {
        float cc = g_c[h];
        g_logits[((size_t)(bA * NHEADS + h)) * TT + ja] = f2_lo(acc0[h]) + f2_hi(acc0[h]) + cc;
        g_logits[((size_t)(bB * NHEADS + h)) * TT + jb] = f2_lo(acc1[h]) + f2_hi(acc1[h]) + cc;
    }
}

// ---------------- kernel 3: stats (max, 1/sum) per (b,h), mask-aware ----------------
__global__ void __launch_bounds__(256) k_stats(const int* __restrict__ mask) {
    int bh = blockIdx.x;
    int b  = bh >> 4;
    const float* row = g_logits + (size_t)bh * TT;
    const int* mrow = mask + (size_t)b * TT;
    int tid = threadIdx.x;

    float x[8];
    float mx = -1e30f;
    #pragma unroll
    for (int r = 0; r < 8; r++) {
        int j = tid + r * 256;
        float v = row[j];
        if (mrow[j] == 0) v = -1e30f;
        x[r] = v;
        mx = fmaxf(mx, v);
    }
    __shared__ float red[8];
    #pragma unroll
    for (int o = 16; o; o >>= 1) mx = fmaxf(mx, __shfl_xor_sync(0xffffffffu, mx, o));
    if ((tid & 31) == 0) red[tid >> 5] = mx;
    __syncthreads();
    mx = red[0];
    #pragma unroll
    for (int w = 1; w < 8; w++) mx = fmaxf(mx, red[w]);

    float sum = 0.f;
    #pragma unroll
    for (int r = 0; r < 8; r++) sum += __expf(x[r] - mx);
    #pragma unroll
    for (int o = 16; o; o >>= 1) sum += __shfl_xor_sync(0xffffffffu, sum, o);
    __syncthreads();
    if ((tid & 31) == 0) red[tid >> 5] = sum;
    __syncthreads();
    if (tid == 0) {
        sum = red[0] + red[1] + red[2] + red[3] + red[4] + red[5] + red[6] + red[7];
        g_stats[bh] = make_float2(mx, __fdividef(1.f, sum));
    }
}

// ---------------- kernel 4: pool ----------------
// Warp-private i-segments: warp w owns i in [w*128, w*128+128), lane owns 4 i.
// Direct LDG.128 (512B/warp/row, coalesced), register double-buffer prefetch
// of 4-row groups, ZERO barriers in the mainloop. Inline masked softmax from
// g_stats. 8 slices of 256 j. 32KB static smem -> 2 CTAs (regs-bound).
__global__ void __launch_bounds__(256) k_pool(const float* __restrict__ hid,
                                              const int* __restrict__ mask) {
    __shared__ __align__(16) ull attn_s[256][NHEADS];   // 32 KB, value duplicated halves
    int slice = blockIdx.x;       // 0..7, 256 j each
    int b     = blockIdx.y;
    int j0    = slice * 256;
    int tid   = threadIdx.x;
    int w     = tid >> 5;
    int l     = tid & 31;

    const int* mrow = mask + (size_t)b * TT + j0;

    // stage masked, normalized attention weights (16 per thread)
    #pragma unroll
    for (int t = 0; t < 16; t++) {
        int idx = t * 256 + tid;
        int h   = idx >> 8;
        int jl  = idx & 255;
        float2 st = g_stats[b * NHEADS + h];
        float lg  = g_logits[((size_t)(b * NHEADS + h)) * TT + j0 + jl];
        float wgt = (mrow[jl] != 0) ? __expf(lg - st.x) * st.y : 0.f;
        unsigned u = __float_as_uint(wgt);
        attn_s[jl][h] = ((ull)u << 32) | u;
    }
    __syncthreads();

    const float* hseg = hid + ((size_t)b * TT + j0) * HID + w * 128 + l * 4;

    ull acc[32];
    #pragma unroll
    for (int t = 0; t < 32; t++) acc[t] = 0ull;

    ulonglong2 cur[4], nxt[4];
    #pragma unroll
    for (int r = 0; r < 4; r++) cur[r] = *(const ulonglong2*)(hseg + (size_t)r * HID);

    #pragma unroll 1
    for (int g = 0; g < 64; g++) {
        if (g < 63) {
            #pragma unroll
            for (int r = 0; r < 4; r++)
                nxt[r] = *(const ulonglong2*)(hseg + (size_t)((g + 1) * 4 + r) * HID);
        }
        #pragma unroll
        for (int r = 0; r < 4; r++) {
            int j = g * 4 + r;
            ulonglong2 u0 = cur[r];
            #pragma unroll
            for (int p = 0; p < 8; p++) {
                ulonglong2 ap = *(const ulonglong2*)&attn_s[j][2 * p];
                FMA2(acc[4 * p + 0], ap.x, u0.x);
                FMA2(acc[4 * p + 1], ap.x, u0.y);
                FMA2(acc[4 * p + 2], ap.y, u0.x);
                FMA2(acc[4 * p + 3], ap.y, u0.y);
            }
        }
        #pragma unroll
        for (int r = 0; r < 4; r++) cur[r] = nxt[r];
    }

    int i0 = w * 128 + l * 4;
    float* pbase = g_partial + (((size_t)slice * BB + b) * NHEADS) * HID + i0;
    #pragma unroll
    for (int h = 0; h < NHEADS; h++) {
        float4 o;
        o.x = f2_lo(acc[2 * h]);     o.y = f2_hi(acc[2 * h]);
        o.z = f2_lo(acc[2 * h + 1]); o.w = f2_hi(acc[2 * h + 1]);
        *(float4*)(pbase + (size_t)h * HID) = o;
    }
}

// ---------------- kernel 5: reduce partials + per-head V projection ----------------
__global__ void __launch_bounds__(256) k_outv(const float* __restrict__ kvw,
                                              const float* __restrict__ kvb) {
    int bh = blockIdx.x;
    int b = bh >> 4;
    int h = bh & 15;
    __shared__ float pooled_s[HID];
    __shared__ float red[4][64];
    int tid = threadIdx.x;
    int i0 = tid * 4;

    float4 s = make_float4(0.f, 0.f, 0.f, 0.f);
    #pragma unroll
    for (int sl = 0; sl < 8; sl++) {
        float4 v = *(const float4*)(g_partial + (((size_t)sl * BB + b) * NHEADS + h) * HID + i0);
        s.x += v.x; s.y += v.y; s.z += v.z; s.w += v.w;
    }
    *(float4*)(pooled_s + i0) = s;
    __syncthreads();

    int d  = tid & 63;
    int qq = tid >> 6;
    const float* wcol = kvw + HID + h * 64 + d;
    float acc = 0.f;
    int ibeg = qq * 256;
    #pragma unroll 4
    for (int i = ibeg; i < ibeg + 256; i++)
        acc += pooled_s[i] * __ldg(wcol + (size_t)i * (2 * HID));
    red[qq][d] = acc;
    __syncthreads();
    if (tid < 64)
        g_outv[b * HID + h * 64 + tid] =
            red[0][tid] + red[1][tid] + red[2][tid] + red[3][tid] + kvb[HID + h * 64 + tid];
}

// ---------------- kernel 6: final GEMM [32,1024] x [1024,1024], c-sliced ----------------
__global__ void __launch_bounds__(256) k_final(const float* __restrict__ outw) {
    int p0 = blockIdx.x * 128;
    int c0 = blockIdx.y * 64;
    __shared__ float outv_s[32][64];
    int tid = threadIdx.x;
    for (int t = tid; t < 32 * 64; t += 256) {
        int bb2 = t >> 6;
        int cc  = t & 63;
        outv_s[bb2][cc] = g_outv[bb2 * HID + c0 + cc];
    }
    __syncthreads();

    int p   = tid & 127;
    int bh2 = tid >> 7;
    float acc[16];
    #pragma unroll
    for (int n = 0; n < 16; n++) acc[n] = 0.f;

    #pragma unroll 4
    for (int cc = 0; cc < 64; cc++) {
        float w = __ldg(outw + (size_t)(c0 + cc) * 1024 + p0 + p);
        #pragma unroll
        for (int n = 0; n < 16; n++) acc[n] += outv_s[bh2 * 16 + n][cc] * w;
    }
    #pragma unroll
    for (int n = 0; n < 16; n++)
        g_fpart[((size_t)blockIdx.y * BB + bh2 * 16 + n) * 1024 + p0 + p] = acc[n];
}

__global__ void k_finred(const float* __restrict__ outb, float* __restrict__ out) {
    int idx = blockIdx.x * 256 + threadIdx.x;
    int b = idx >> 10;
    int p = idx & 1023;
    float s = outb[p];
    #pragma unroll
    for (int cs = 0; cs < 16; cs++) s += g_fpart[((size_t)cs * BB + b) * 1024 + p];
    out[idx] = s;
}

// ---------------- launch ----------------
extern "C" void kernel_launch(void* const* d_in, const int* in_sizes, int n_in,
                              void* d_out, int out_size) {
    const float* hid  = (const float*)d_in[0];
    const int*   mask = (const int*)  d_in[1];
    const float* kvw  = (const float*)d_in[2];
    const float* kvb  = (const float*)d_in[3];
    const float* outw = (const float*)d_in[4];
    const float* outb = (const float*)d_in[5];
    const float* q    = (const float*)d_in[6];
    float* out = (float*)d_out;

    cudaFuncSetAttribute(k_logits, cudaFuncAttributeMaxDynamicSharedMemorySize, 49152);

    k_wq     <<<2048, 256>>>(q, kvw, kvb);
    k_logits <<<256, 128, 49152>>>(hid);
    k_stats  <<<512, 256>>>(mask);
    k_pool   <<<dim3(8, 32), 256>>>(hid, mask);
    k_outv   <<<512, 256>>>(kvw, kvb);
    k_final  <<<dim3(8, 16), 256>>>(outw);
    k_finred <<<128, 256>>>(outb, out);
}

// round 7
// speedup vs baseline: 1.4792x; 1.4792x over previous
#include <cuda_runtime.h>
#include <cstdint>

#define NHEADS 16
#define HID    1024
#define TT     2048
#define BB     32

typedef unsigned long long ull;

// ---------------- device scratch (no allocations allowed) ----------------
__device__ float g_wq[NHEADS * HID];
__device__ float g_c[NHEADS];
__device__ float g_logits[BB * NHEADS * TT];          // reused in-place as attn
__device__ float g_partial[16 * BB * NHEADS * HID];   // pass-2 partials
__device__ float g_outv[BB * HID];
__device__ float g_fpart[16 * BB * HID];

#define FMA2(c, a, b) asm("fma.rn.f32x2 %0, %1, %2, %0;" : "+l"(c) : "l"(a), "l"(b))
static __device__ __forceinline__ float f2_lo(ull v) { return __uint_as_float((unsigned)(v & 0xffffffffull)); }
static __device__ __forceinline__ float f2_hi(ull v) { return __uint_as_float((unsigned)(v >> 32)); }

static __device__ __forceinline__ unsigned smaddr(const void* p) {
    return (unsigned)__cvta_generic_to_shared(p);
}
#define CP16(dst, src)  asm volatile("cp.async.cg.shared.global [%0], [%1], 16;" :: "r"(dst), "l"(src))
#define CP_COMMIT()     asm volatile("cp.async.commit_group;" ::: "memory")
#define CP_WAIT2()      asm volatile("cp.async.wait_group 2;" ::: "memory")

// ---------------- kernel 1: fold query into kv_w (k half) ----------------
__global__ void k_wq(const float* __restrict__ q,
                     const float* __restrict__ kvw,
                     const float* __restrict__ kvb) {
    int w = blockIdx.x * (blockDim.x >> 5) + (threadIdx.x >> 5);
    int lane = threadIdx.x & 31;
    if (w < NHEADS * HID) {
        int h = w & (NHEADS - 1);
        int i = w >> 4;
        const float* wr = kvw + (size_t)i * (2 * HID) + h * 64;
        const float* qr = q + h * 64;
        float s = qr[lane] * wr[lane] + qr[lane + 32] * wr[lane + 32];
        #pragma unroll
        for (int o = 16; o; o >>= 1) s += __shfl_xor_sync(0xffffffffu, s, o);
        if (lane == 0) g_wq[h * HID + i] = 0.125f * s;
    }
    if (blockIdx.x == 0 && threadIdx.x < NHEADS) {
        int h = threadIdx.x;
        float s = 0.f;
        for (int d = 0; d < 64; d++) s += q[h * 64 + d] * kvb[h * 64 + d];
        g_c[h] = 0.125f * s;
    }
}

// ---------------- kernel 2: logits ----------------
// 128 threads, TWO rows each (tid, tid+128), 256 rows/block. 3-stage cp.async
// ring over 16-k chunks. Row pitch 20 floats: LDS.128 phase banks 20*l mod 32
// all distinct -> conflict-free. wq broadcasts amortized over 2 rows.
// 60KB dynamic + 3KB static -> 3 CTAs = 12 warps/SM.
#define LCH 16
#define HP  20
__global__ void __launch_bounds__(128) k_logits(const float* __restrict__ hid) {
    extern __shared__ __align__(16) float hsm[];        // [3][256][20]
    __shared__ __align__(16) float wq_s[3][NHEADS][LCH];
    int tid = threadIdx.x;
    const float* hblk = hid + (size_t)blockIdx.x * 256 * HID;

    ull acc0[NHEADS], acc1[NHEADS];
    #pragma unroll
    for (int h = 0; h < NHEADS; h++) { acc0[h] = 0ull; acc1[h] = 0ull; }

    // stage st <- k chunk kc : 256 rows x 16 floats = 1024 float4, 8/thread
    #define LFILL(st, kc)                                                          \
        do {                                                                       \
            _Pragma("unroll")                                                      \
            for (int p = 0; p < 8; p++) {                                          \
                int idx = p * 128 + tid;                                           \
                int row = idx >> 2;                                                \
                int q4  = (idx & 3) * 4;                                           \
                CP16(smaddr(hsm + ((st) * 256 + row) * HP + q4),                   \
                     hblk + (size_t)row * HID + (kc) + q4);                        \
            }                                                                      \
            if (tid < 64) {                                                        \
                int hh = tid >> 2;                                                 \
                int kq = (tid & 3) * 4;                                            \
                CP16(smaddr(&wq_s[st][hh][kq]), g_wq + hh * HID + (kc) + kq);      \
            }                                                                      \
        } while (0)

    LFILL(0, 0);   CP_COMMIT();
    LFILL(1, LCH); CP_COMMIT();

    for (int c = 0; c < HID / LCH; c++) {
        if (c + 2 < HID / LCH) {
            int st = (c + 2) % 3;
            int kc = (c + 2) * LCH;
            LFILL(st, kc);
        }
        CP_COMMIT();
        CP_WAIT2();
        __syncthreads();

        int buf = c % 3;
        const float* r0 = hsm + (buf * 256 + tid) * HP;
        const float* r1 = hsm + (buf * 256 + tid + 128) * HP;
        #pragma unroll
        for (int k = 0; k < LCH; k += 8) {
            ulonglong2 a0 = *(const ulonglong2*)(r0 + k);
            ulonglong2 b0 = *(const ulonglong2*)(r0 + k + 4);
            ulonglong2 a1 = *(const ulonglong2*)(r1 + k);
            ulonglong2 b1 = *(const ulonglong2*)(r1 + k + 4);
            #pragma unroll
            for (int h = 0; h < NHEADS; h++) {
                ulonglong2 w0 = *(const ulonglong2*)&wq_s[buf][h][k];
                ulonglong2 w1 = *(const ulonglong2*)&wq_s[buf][h][k + 4];
                FMA2(acc0[h], a0.x, w0.x);
                FMA2(acc0[h], a0.y, w0.y);
                FMA2(acc0[h], b0.x, w1.x);
                FMA2(acc0[h], b0.y, w1.y);
                FMA2(acc1[h], a1.x, w0.x);
                FMA2(acc1[h], a1.y, w0.y);
                FMA2(acc1[h], b1.x, w1.x);
                FMA2(acc1[h], b1.y, w1.y);
            }
        }
        __syncthreads();
    }

    size_t jA = (size_t)blockIdx.x * 256 + tid;
    size_t jB = jA + 128;
    int bA = (int)(jA >> 11), ja = (int)(jA & 2047);
    int bB = (int)(jB >> 11), jb = (int)(jB & 2047);
    #pragma unroll
    for (int h = 0; h < NHEADS; h++) {
        float cc = g_c[h];
        g_logits[((size_t)(bA * NHEADS + h)) * TT + ja] = f2_lo(acc0[h]) + f2_hi(acc0[h]) + cc;
        g_logits[((size_t)(bB * NHEADS + h)) * TT + jb] = f2_lo(acc1[h]) + f2_hi(acc1[h]) + cc;
    }
}

// ---------------- kernel 3: softmax (in-place) ----------------
__global__ void __launch_bounds__(256) k_softmax(const int* __restrict__ mask) {
    int bh = blockIdx.x;
    int b  = bh >> 4;
    float* row = g_logits + (size_t)bh * TT;
    const int* mrow = mask + (size_t)b * TT;
    int tid = threadIdx.x;

    float x[8];
    float mx = -1e30f;
    #pragma unroll
    for (int r = 0; r < 8; r++) {
        int j = tid + r * 256;
        float v = row[j];
        if (mrow[j] == 0) v = -1e30f;
        x[r] = v;
        mx = fmaxf(mx, v);
    }
    __shared__ float red[8];
    #pragma unroll
    for (int o = 16; o; o >>= 1) mx = fmaxf(mx, __shfl_xor_sync(0xffffffffu, mx, o));
    if ((tid & 31) == 0) red[tid >> 5] = mx;
    __syncthreads();
    mx = red[0];
    #pragma unroll
    for (int w = 1; w < 8; w++) mx = fmaxf(mx, red[w]);

    float sum = 0.f;
    #pragma unroll
    for (int r = 0; r < 8; r++) { float e = __expf(x[r] - mx); x[r] = e; sum += e; }
    #pragma unroll
    for (int o = 16; o; o >>= 1) sum += __shfl_xor_sync(0xffffffffu, sum, o);
    __syncthreads();
    if ((tid & 31) == 0) red[tid >> 5] = sum;
    __syncthreads();
    sum = red[0] + red[1] + red[2] + red[3] + red[4] + red[5] + red[6] + red[7];
    float inv = __fdividef(1.f, sum);
    #pragma unroll
    for (int r = 0; r < 8; r++) row[tid + r * 256] = x[r] * inv;
}

// ---------------- kernel 4: pool (R4-measured version, unchanged) ----------------
__global__ void __launch_bounds__(256) k_pool(const float* __restrict__ hid) {
    extern __shared__ __align__(16) float hsm2[];        // [3][8][1024]
    __shared__ __align__(16) ull attn_s[128][NHEADS];
    int slice = blockIdx.x;       // 16 slices of 128 j
    int b     = blockIdx.y;
    int j0    = slice * 128;
    int tid   = threadIdx.x;

    const float* hbase = hid + ((size_t)b * TT + j0) * HID;

    #pragma unroll
    for (int st = 0; st < 2; st++) {
        float* dstb = hsm2 + st * 8192;
        const float* srcb = hbase + (size_t)st * 8 * HID;
        #pragma unroll
        for (int p = 0; p < 8; p++) {
            int idx = p * 256 + tid;
            int row = idx >> 8;
            int col = (idx & 255) * 4;
            CP16(smaddr(dstb + row * 1024 + col), srcb + (size_t)row * HID + col);
        }
        CP_COMMIT();
    }

    #pragma unroll
    for (int t = 0; t < 8; t++) {
        int idx  = t * 256 + tid;
        int jloc = idx & 127;
        int h    = idx >> 7;
        float a = g_logits[((size_t)(b * NHEADS + h)) * TT + j0 + jloc];
        unsigned u = __float_as_uint(a);
        attn_s[jloc][h] = ((ull)u << 32) | u;
    }

    int i0 = tid * 4;
    ull acc[32];
    #pragma unroll
    for (int t = 0; t < 32; t++) acc[t] = 0ull;

    for (int s = 0; s < 16; s++) {
        if (s + 2 < 16) {
            float* dstb = hsm2 + ((s + 2) % 3) * 8192;
            const float* srcb = hbase + (size_t)(s + 2) * 8 * HID;
            #pragma unroll
            for (int p = 0; p < 8; p++) {
                int idx = p * 256 + tid;
                int row = idx >> 8;
                int col = (idx & 255) * 4;
                CP16(smaddr(dstb + row * 1024 + col), srcb + (size_t)row * HID + col);
            }
        }
        CP_COMMIT();
        CP_WAIT2();
        __syncthreads();

        const float* buf = hsm2 + (s % 3) * 8192;
        #pragma unroll
        for (int jj = 0; jj < 8; jj++) {
            int j = s * 8 + jj;
            ulonglong2 u0 = *(const ulonglong2*)(buf + jj * 1024 + i0);
            #pragma unroll
            for (int p = 0; p < 8; p++) {
                ulonglong2 ap = *(const ulonglong2*)&attn_s[j][2 * p];
                FMA2(acc[4 * p + 0], ap.x, u0.x);
                FMA2(acc[4 * p + 1], ap.x, u0.y);
                FMA2(acc[4 * p + 2], ap.y, u0.x);
                FMA2(acc[4 * p + 3], ap.y, u0.y);
            }
        }
        __syncthreads();
    }

    float* pbase = g_partial + (((size_t)slice * BB + b) * NHEADS) * HID + i0;
    #pragma unroll
    for (int h = 0; h < NHEADS; h++) {
        float4 o;
        o.x = f2_lo(acc[2 * h]);     o.y = f2_hi(acc[2 * h]);
        o.z = f2_lo(acc[2 * h + 1]); o.w = f2_hi(acc[2 * h + 1]);
        *(float4*)(pbase + (size_t)h * HID) = o;
    }
}

// ---------------- kernel 5: reduce partials + per-head V projection ----------------
__global__ void __launch_bounds__(256) k_outv(const float* __restrict__ kvw,
                                              const float* __restrict__ kvb) {
    int bh = blockIdx.x;
    int b = bh >> 4;
    int h = bh & 15;
    __shared__ float pooled_s[HID];
    __shared__ float red[4][64];
    int tid = threadIdx.x;
    int i0 = tid * 4;

    float4 s = make_float4(0.f, 0.f, 0.f, 0.f);
    #pragma unroll
    for (int sl = 0; sl < 16; sl++) {
        float4 v = *(const float4*)(g_partial + (((size_t)sl * BB + b) * NHEADS + h) * HID + i0);
        s.x += v.x; s.y += v.y; s.z += v.z; s.w += v.w;
    }
    *(float4*)(pooled_s + i0) = s;
    __syncthreads();

    int d  = tid & 63;
    int qq = tid >> 6;
    const float* wcol = kvw + HID + h * 64 + d;
    float acc = 0.f;
    int ibeg = qq * 256;
    #pragma unroll 4
    for (int i = ibeg; i < ibeg + 256; i++)
        acc += pooled_s[i] * __ldg(wcol + (size_t)i * (2 * HID));
    red[qq][d] = acc;
    __syncthreads();
    if (tid < 64)
        g_outv[b * HID + h * 64 + tid] =
            red[0][tid] + red[1][tid] + red[2][tid] + red[3][tid] + kvb[HID + h * 64 + tid];
}

// ---------------- kernel 6: final GEMM [32,1024] x [1024,1024], c-sliced ----------------
__global__ void __launch_bounds__(256) k_final(const float* __restrict__ outw) {
    int p0 = blockIdx.x * 128;
    int c0 = blockIdx.y * 64;
    __shared__ float outv_s[32][64];
    int tid = threadIdx.x;
    for (int t = tid; t < 32 * 64; t += 256) {
        int bb2 = t >> 6;
        int cc  = t & 63;
        outv_s[bb2][cc] = g_outv[bb2 * HID + c0 + cc];
    }
    __syncthreads();

    int p   = tid & 127;
    int bh2 = tid >> 7;
    float acc[16];
    #pragma unroll
    for (int n = 0; n < 16; n++) acc[n] = 0.f;

    #pragma unroll 4
    for (int cc = 0; cc < 64; cc++) {
        float w = __ldg(outw + (size_t)(c0 + cc) * 1024 + p0 + p);
        #pragma unroll
        for (int n = 0; n < 16; n++) acc[n] += outv_s[bh2 * 16 + n][cc] * w;
    }
    #pragma unroll
    for (int n = 0; n < 16; n++)
        g_fpart[((size_t)blockIdx.y * BB + bh2 * 16 + n) * 1024 + p0 + p] = acc[n];
}

__global__ void k_finred(const float* __restrict__ outb, float* __restrict__ out) {
    int idx = blockIdx.x * 256 + threadIdx.x;
    int b = idx >> 10;
    int p = idx & 1023;
    float s = outb[p];
    #pragma unroll
    for (int cs = 0; cs < 16; cs++) s += g_fpart[((size_t)cs * BB + b) * 1024 + p];
    out[idx] = s;
}

// ---------------- launch ----------------
extern "C" void kernel_launch(void* const* d_in, const int* in_sizes, int n_in,
                              void* d_out, int out_size) {
    const float* hid  = (const float*)d_in[0];
    const int*   mask = (const int*)  d_in[1];
    const float* kvw  = (const float*)d_in[2];
    const float* kvb  = (const float*)d_in[3];
    const float* outw = (const float*)d_in[4];
    const float* outb = (const float*)d_in[5];
    const float* q    = (const float*)d_in[6];
    float* out = (float*)d_out;

    cudaFuncSetAttribute(k_logits, cudaFuncAttributeMaxDynamicSharedMemorySize, 61440);
    cudaFuncSetAttribute(k_pool,   cudaFuncAttributeMaxDynamicSharedMemorySize, 98304);

    k_wq     <<<2048, 256>>>(q, kvw, kvb);
    k_logits <<<256, 128, 61440>>>(hid);
    k_softmax<<<512, 256>>>(mask);
    k_pool   <<<dim3(16, 32), 256, 98304>>>(hid);
    k_outv   <<<512, 256>>>(kvw, kvb);
    k_final  <<<dim3(8, 16), 256>>>(outw);
    k_finred <<<128, 256>>>(outb, out);
}